// round 8
// baseline (speedup 1.0000x reference)
#include <cuda_runtime.h>
#include <cstdint>

typedef unsigned long long u64;

#define GROUPS 8
#define CDIM 32
#define ROWS_PER_GROUP 262144
#define TOTAL_ROWS (GROUPS * ROWS_PER_GROUP)
#define EPSV 1e-5f
#define TITER 5

// ---- pass 1 config ----
#define P1_BLOCKS_PER_GROUP 256
#define P1_GRID (GROUPS * P1_BLOCKS_PER_GROUP)   // 2048
#define P1_ROWS 1024
#define P1_WROWS 128
#define P1_CHUNK 16
#define P1_CHUNKS (P1_WROWS / P1_CHUNK)          // 8
// staging layout per pair: 4 channel-blocks (8 ch each) at u64 stride 10;
// pair stride 40 u64 (=80 words) -> conflict-free 8x8-tile loads
#define BLK_STRIDE 10
#define PSTRIDE 40
#define WBUF_U64 (8 * PSTRIDE)                   // 320 u64 = 2560 B per warp

// ---- reduction stage ----
#define RED_SLICES 32
#define RED_FOLD (P1_BLOCKS_PER_GROUP / RED_SLICES)

// ---- pass 2 config ----
#define P2_TPB 128
#define P2_ROWS 256
#define P2_GRID (TOTAL_ROWS / P2_ROWS)           // 8192
#define ZST 36                                   // floats per staged row (16B-aligned float4 reads)

// ---- scratch ----
__device__ __align__(16) float gCovPart[P1_GRID * 1024];
__device__ __align__(16) float gSumPart[P1_GRID * 32];
__device__ __align__(16) float gCov2[GROUPS * RED_SLICES * 1024];
__device__ __align__(16) float gSum2[GROUPS * RED_SLICES * 32];
__device__ __align__(16) float gMt[GROUPS * 1024];
__device__ __align__(16) float gBias[GROUPS * 32];

// ---- f32x2 helpers ----
__device__ __forceinline__ u64 pack2(float a, float b) {
    u64 r; asm("mov.b64 %0, {%1, %2};" : "=l"(r) : "f"(a), "f"(b)); return r;
}
__device__ __forceinline__ float2 unpack2(u64 v) {
    float2 r; asm("mov.b64 {%0, %1}, %2;" : "=f"(r.x), "=f"(r.y) : "l"(v)); return r;
}
__device__ __forceinline__ u64 ffma2(u64 a, u64 b, u64 c) {
    u64 d; asm("fma.rn.f32x2 %0, %1, %2, %3;" : "=l"(d) : "l"(a), "l"(b), "l"(c)); return d;
}

// ============================================================================
// Kernel 1: partial C = sum z z^T + channel sums. 8x8 lane tiles.
// Lane l: tile = l&15 (ti=(l>>2)&3, tj=l&3), half h = l>>4 handles pairs
// p = 2*pp + h. Per pair: zi,zj = 8 LDS.128 (128 B) feeding 64 FFMA2
// (128 MACs) -> 1.0 B/MAC. acc[8][8] u64; halves merged by SHFL at the end.
// ============================================================================
__global__ __launch_bounds__(256, 1) void k1_stats(const float4* __restrict__ in4) {
    __shared__ __align__(16) unsigned char smem_raw[32768];
    float* red = (float*)smem_raw;

    const int t   = threadIdx.x;
    const int bid = blockIdx.x;
    const int w   = t >> 5;
    const int l   = t & 31;
    const int ti  = (l >> 2) & 3;
    const int tj  = l & 3;
    const int h   = l >> 4;
    const int k   = l & 7;      // staging: float4 slot (channels 4k..4k+3)
    const int p0  = l >> 3;     // staging: base pair

    u64* wbuf = (u64*)(smem_raw + w * (WBUF_U64 * 8));

    u64 acc[8][8];
#pragma unroll
    for (int i = 0; i < 8; i++)
#pragma unroll
        for (int j = 0; j < 8; j++) acc[i][j] = 0ull;

    float msum[4] = {0.f, 0.f, 0.f, 0.f};

    const long wbase4 = (long)bid * (P1_ROWS * 8) + (long)w * (P1_WROWS * 8);

    // staging store target for channels 4k..4k+3: block k>>1, in-block u64 4*(k&1)
    const int stoff = (k >> 1) * BLK_STRIDE + 4 * (k & 1);

    float4 va0 = in4[wbase4 + (2 * p0) * 8 + k];
    float4 vb0 = in4[wbase4 + (2 * p0 + 1) * 8 + k];
    float4 va1 = in4[wbase4 + (2 * (p0 + 4)) * 8 + k];
    float4 vb1 = in4[wbase4 + (2 * (p0 + 4) + 1) * 8 + k];

    for (int c = 0; c < P1_CHUNKS; c++) {
        __syncwarp();
        {
            msum[0] += va0.x + vb0.x + va1.x + vb1.x;
            msum[1] += va0.y + vb0.y + va1.y + vb1.y;
            msum[2] += va0.z + vb0.z + va1.z + vb1.z;
            msum[3] += va0.w + vb0.w + va1.w + vb1.w;
            ulonglong2* dst0 = (ulonglong2*)(wbuf + p0 * PSTRIDE + stoff);
            dst0[0] = make_ulonglong2(pack2(va0.x, vb0.x), pack2(va0.y, vb0.y));
            dst0[1] = make_ulonglong2(pack2(va0.z, vb0.z), pack2(va0.w, vb0.w));
            ulonglong2* dst1 = (ulonglong2*)(wbuf + (p0 + 4) * PSTRIDE + stoff);
            dst1[0] = make_ulonglong2(pack2(va1.x, vb1.x), pack2(va1.y, vb1.y));
            dst1[1] = make_ulonglong2(pack2(va1.z, vb1.z), pack2(va1.w, vb1.w));
        }
        if (c + 1 < P1_CHUNKS) {
            long nb = wbase4 + (long)(c + 1) * (P1_CHUNK * 8);
            va0 = in4[nb + (2 * p0) * 8 + k];
            vb0 = in4[nb + (2 * p0 + 1) * 8 + k];
            va1 = in4[nb + (2 * (p0 + 4)) * 8 + k];
            vb1 = in4[nb + (2 * (p0 + 4) + 1) * 8 + k];
        }
        __syncwarp();
#pragma unroll
        for (int pp = 0; pp < 4; pp++) {
            const int p = 2 * pp + h;
            const ulonglong2* rowp = (const ulonglong2*)(wbuf + p * PSTRIDE);
            u64 zi[8], zj[8];
#pragma unroll
            for (int q = 0; q < 4; q++) {
                ulonglong2 v = rowp[5 * ti + q];
                zi[2 * q] = v.x; zi[2 * q + 1] = v.y;
            }
#pragma unroll
            for (int q = 0; q < 4; q++) {
                ulonglong2 v = rowp[5 * tj + q];
                zj[2 * q] = v.x; zj[2 * q + 1] = v.y;
            }
#pragma unroll
            for (int i = 0; i < 8; i++)
#pragma unroll
                for (int j = 0; j < 8; j++)
                    acc[i][j] = ffma2(zi[i], zj[j], acc[i][j]);
        }
    }
    __syncthreads();
    // ---- merge halves (l <-> l^16) and write per-warp partials ----
#pragma unroll
    for (int i = 0; i < 8; i++)
#pragma unroll
        for (int j = 0; j < 8; j++) {
            float2 x = unpack2(acc[i][j]);
            float s = x.x + x.y;
            s += __shfl_xor_sync(0xffffffffu, s, 16);
            if (h == 0)
                red[w * 1024 + (8 * ti + i) * 32 + (8 * tj + j)] = s;
        }
    __syncthreads();
    // ---- block reduce C (deterministic order) ----
#pragma unroll
    for (int r = 0; r < 4; r++) {
        int e = t + 256 * r;
        float s = 0.f;
#pragma unroll
        for (int ww = 0; ww < 8; ww++) s += red[ww * 1024 + e];
        gCovPart[(long)bid * 1024 + e] = s;
    }
    __syncthreads();
    // ---- block reduce channel sums ----
    red[t * 4 + 0] = msum[0]; red[t * 4 + 1] = msum[1];
    red[t * 4 + 2] = msum[2]; red[t * 4 + 3] = msum[3];
    __syncthreads();
    if (t < 32) {
        int kk = t >> 2, i = t & 3;
        float s = 0.f;
#pragma unroll 8
        for (int q = 0; q < 32; q++) s += red[(q * 8 + kk) * 4 + i];
        gSumPart[bid * 32 + t] = s;
    }
}

// ============================================================================
// Kernel 1b: fold 2048 partials -> 256
// ============================================================================
__global__ __launch_bounds__(256) void k_red() {
    const int t = threadIdx.x;
    const int bid = blockIdx.x;
    const long base = (long)bid * RED_FOLD;

#pragma unroll
    for (int r = 0; r < 4; r++) {
        int e = t + 256 * r;
        float s = 0.f;
#pragma unroll
        for (int f = 0; f < RED_FOLD; f++) s += gCovPart[(base + f) * 1024 + e];
        gCov2[(long)bid * 1024 + e] = s;
    }
    if (t < 32) {
        float s = 0.f;
#pragma unroll
        for (int f = 0; f < RED_FOLD; f++) s += gSumPart[(base + f) * 32 + t];
        gSum2[bid * 32 + t] = s;
    }
}

// ============================================================================
// Kernel 2: final reduce, build S, normalize, Newton-Schulz, emit Mt+bias.
// ============================================================================
__global__ __launch_bounds__(1024) void k_solve() {
    __shared__ float S[1024], B[1024], T1[1024], T2[1024];
    __shared__ float mu[32];
    __shared__ float redw[32];
    __shared__ float normsh;

    const int t = threadIdx.x;
    const int g = blockIdx.x;
    const int i = t >> 5, j = t & 31;

    float cv = 0.f;
    const float* cp = gCov2 + (long)g * RED_SLICES * 1024;
#pragma unroll 8
    for (int bb = 0; bb < RED_SLICES; bb++) cv += cp[bb * 1024 + t];
    if (t < 32) {
        float s = 0.f;
        const float* sp = gSum2 + g * RED_SLICES * 32;
#pragma unroll 8
        for (int bb = 0; bb < RED_SLICES; bb++) s += sp[bb * 32 + t];
        mu[t] = s * (1.0f / (float)ROWS_PER_GROUP);
    }
    __syncthreads();

    float sij = cv - (float)ROWS_PER_GROUP * mu[i] * mu[j] + ((i == j) ? EPSV : 0.f);

    float v = sij * sij;
#pragma unroll
    for (int o = 16; o; o >>= 1) v += __shfl_xor_sync(0xffffffffu, v, o);
    if (j == 0) redw[i] = v;
    __syncthreads();
    if (t < 32) {
        float x = redw[t];
#pragma unroll
        for (int o = 16; o; o >>= 1) x += __shfl_xor_sync(0xffffffffu, x, o);
        if (t == 0) normsh = sqrtf(x);
    }
    __syncthreads();
    const float nrm = normsh;

    S[t] = sij / nrm;
    B[t] = (i == j) ? 1.f : 0.f;
    __syncthreads();

    for (int it = 0; it < TITER; it++) {
        float s1 = 0.f;
#pragma unroll
        for (int kk = 0; kk < 32; kk++) s1 += B[i * 32 + kk] * B[kk * 32 + j];
        T1[t] = s1; __syncthreads();
        float s2 = 0.f;
#pragma unroll
        for (int kk = 0; kk < 32; kk++) s2 += T1[i * 32 + kk] * B[kk * 32 + j];
        T2[t] = s2; __syncthreads();
        float s3 = 0.f;
#pragma unroll
        for (int kk = 0; kk < 32; kk++) s3 += T2[i * 32 + kk] * S[kk * 32 + j];
        float nb = 1.5f * B[t] - 0.5f * s3;
        __syncthreads();
        B[t] = nb;
        __syncthreads();
    }

    const float inv = rsqrtf(nrm);
    float mt = B[j * 32 + i] * inv;
    gMt[g * 1024 + t] = mt;
    T1[t] = mt;
    __syncthreads();
    if (t < 32) {
        float bsum = 0.f;
#pragma unroll
        for (int d = 0; d < 32; d++) bsum += mu[d] * T1[d * 32 + t];
        gBias[g * 32 + t] = -bsum;
    }
}

// ============================================================================
// Kernel 3: out[n] = z[n] @ Mt + bias. 128 threads, 256 rows, 8 rows/thread.
// z read as LDS.128 per 4 d's (ZST=36 -> 16B aligned, conflict-free).
// ============================================================================
__global__ __launch_bounds__(P2_TPB, 4) void k2_apply(const float4* __restrict__ in4,
                                                      float4* __restrict__ out4) {
    __shared__ __align__(16) float zbuf[P2_ROWS * ZST];  // 36864 B
    __shared__ __align__(16) u64 mt2[512];
    __shared__ u64 bias2[16];

    const int t = threadIdx.x;
    const int g = blockIdx.x >> 10;          // 1024 blocks per group

    const u64* mtg = (const u64*)gMt + g * 512;
#pragma unroll
    for (int i = 0; i < 4; i++) mt2[t + 128 * i] = mtg[t + 128 * i];
    if (t < 16) bias2[t] = ((const u64*)gBias)[g * 16 + t];

    const int m = t & 3;
    const int q = t >> 2;                    // 0..31
    const long R0 = (long)blockIdx.x * P2_ROWS;

    // ---- stage 256 rows: coalesced LDG.128 -> STS.128 ----
#pragma unroll
    for (int i = 0; i < 16; i++) {
        int f = t + 128 * i;
        int row = f >> 3, sl = f & 7;
        float4 v = in4[R0 * 8 + f];
        *(float4*)(zbuf + row * ZST + 4 * sl) = v;
    }
    __syncthreads();

    u64 acc[8][4];
#pragma unroll
    for (int rr = 0; rr < 8; rr++)
#pragma unroll
        for (int jj = 0; jj < 4; jj++) acc[rr][jj] = bias2[m * 4 + jj];

    const ulonglong2* mtv = (const ulonglong2*)mt2;
#pragma unroll 2
    for (int dp2 = 0; dp2 < 8; dp2++) {
        const int d0 = 4 * dp2;
        ulonglong2 a0 = mtv[(d0 + 0) * 8 + m * 2 + 0];
        ulonglong2 b0 = mtv[(d0 + 0) * 8 + m * 2 + 1];
        ulonglong2 a1 = mtv[(d0 + 1) * 8 + m * 2 + 0];
        ulonglong2 b1 = mtv[(d0 + 1) * 8 + m * 2 + 1];
        ulonglong2 a2 = mtv[(d0 + 2) * 8 + m * 2 + 0];
        ulonglong2 b2 = mtv[(d0 + 2) * 8 + m * 2 + 1];
        ulonglong2 a3 = mtv[(d0 + 3) * 8 + m * 2 + 0];
        ulonglong2 b3 = mtv[(d0 + 3) * 8 + m * 2 + 1];
#pragma unroll
        for (int rr = 0; rr < 8; rr++) {
            float4 z4 = *(const float4*)(zbuf + (q + 32 * rr) * ZST + d0);
            u64 z0 = pack2(z4.x, z4.x);
            u64 z1 = pack2(z4.y, z4.y);
            u64 z2 = pack2(z4.z, z4.z);
            u64 z3 = pack2(z4.w, z4.w);
            acc[rr][0] = ffma2(z0, a0.x, acc[rr][0]);
            acc[rr][1] = ffma2(z0, a0.y, acc[rr][1]);
            acc[rr][2] = ffma2(z0, b0.x, acc[rr][2]);
            acc[rr][3] = ffma2(z0, b0.y, acc[rr][3]);
            acc[rr][0] = ffma2(z1, a1.x, acc[rr][0]);
            acc[rr][1] = ffma2(z1, a1.y, acc[rr][1]);
            acc[rr][2] = ffma2(z1, b1.x, acc[rr][2]);
            acc[rr][3] = ffma2(z1, b1.y, acc[rr][3]);
            acc[rr][0] = ffma2(z2, a2.x, acc[rr][0]);
            acc[rr][1] = ffma2(z2, a2.y, acc[rr][1]);
            acc[rr][2] = ffma2(z2, b2.x, acc[rr][2]);
            acc[rr][3] = ffma2(z2, b2.y, acc[rr][3]);
            acc[rr][0] = ffma2(z3, a3.x, acc[rr][0]);
            acc[rr][1] = ffma2(z3, a3.y, acc[rr][1]);
            acc[rr][2] = ffma2(z3, b3.x, acc[rr][2]);
            acc[rr][3] = ffma2(z3, b3.y, acc[rr][3]);
        }
    }

#pragma unroll
    for (int rr = 0; rr < 8; rr++) {
        float2 p0 = unpack2(acc[rr][0]), p1 = unpack2(acc[rr][1]);
        float2 p2 = unpack2(acc[rr][2]), p3 = unpack2(acc[rr][3]);
        long rowb = (R0 + q + 32 * rr) * 8;
        out4[rowb + m * 2 + 0] = make_float4(p0.x, p0.y, p1.x, p1.y);
        out4[rowb + m * 2 + 1] = make_float4(p2.x, p2.y, p3.x, p3.y);
    }
}

// ============================================================================
extern "C" void kernel_launch(void* const* d_in, const int* in_sizes, int n_in,
                              void* d_out, int out_size) {
    const float4* in4 = (const float4*)d_in[0];
    float4* out4 = (float4*)d_out;

    k1_stats<<<P1_GRID, 256>>>(in4);
    k_red<<<GROUPS * RED_SLICES, 256>>>();
    k_solve<<<GROUPS, 1024>>>();
    k2_apply<<<P2_GRID, P2_TPB>>>(in4, out4);
}

// round 9
// speedup vs baseline: 1.1593x; 1.1593x over previous
#include <cuda_runtime.h>
#include <cstdint>

typedef unsigned long long u64;

#define GROUPS 8
#define CDIM 32
#define ROWS_PER_GROUP 262144
#define TOTAL_ROWS (GROUPS * ROWS_PER_GROUP)
#define EPSV 1e-5f
#define TITER 5

// ---- pass 1 config ----
#define P1_BLOCKS_PER_GROUP 256
#define P1_GRID (GROUPS * P1_BLOCKS_PER_GROUP)   // 2048
#define P1_ROWS 1024
#define P1_WROWS 128
#define P1_CHUNK 16
#define P1_CHUNKS (P1_WROWS / P1_CHUNK)          // 8
#define ZR 36                                    // floats per staged sample row (16B-aligned)
#define WBUF_F (P1_CHUNK * ZR)                   // 576 floats = 2304 B per warp

// ---- reduction stage ----
#define RED_SLICES 32
#define RED_FOLD (P1_BLOCKS_PER_GROUP / RED_SLICES)

// ---- pass 2 config (exact revert to measured-103.5 variant) ----
#define P2_TPB 128
#define P2_ROWS 256
#define P2_GRID (TOTAL_ROWS / P2_ROWS)           // 8192
#define ZST 34

// ---- scratch ----
__device__ __align__(16) float gCovPart[P1_GRID * 1024];
__device__ __align__(16) float gSumPart[P1_GRID * 32];
__device__ __align__(16) float gCov2[GROUPS * RED_SLICES * 1024];
__device__ __align__(16) float gSum2[GROUPS * RED_SLICES * 32];
__device__ __align__(16) float gMt[GROUPS * 1024];
__device__ __align__(16) float gBias[GROUPS * 32];

// ---- f32x2 helpers ----
__device__ __forceinline__ u64 pack2(float a, float b) {
    u64 r; asm("mov.b64 %0, {%1, %2};" : "=l"(r) : "f"(a), "f"(b)); return r;
}
__device__ __forceinline__ float2 unpack2(u64 v) {
    float2 r; asm("mov.b64 {%0, %1}, %2;" : "=f"(r.x), "=f"(r.y) : "l"(v)); return r;
}
__device__ __forceinline__ u64 ffma2(u64 a, u64 b, u64 c) {
    u64 d; asm("fma.rn.f32x2 %0, %1, %2, %3;" : "=l"(d) : "l"(a), "l"(b), "l"(c)); return d;
}

// ============================================================================
// Kernel 1: partial C = sum z z^T + channel sums. CHANNEL-PAIRED f32x2.
// Staging is RAW row-major [sample][32ch] (stride 36 floats, no packing).
// Lane l: half h=l>>4 (even/odd samples), tile ti=(l>>2)&3, tj=l&3.
// Per sample: zi = 2 LDS.128 (8 scalar channels, splatted in regs),
// zj = 2 LDS.128 (8 channels as 4 u64 pairs). 32 FFMA2 = 64 MACs from
// 64 B of LDS -> 1.0 B/MAC with acc[8][4] = 64 regs only.
// Halves merged by 2 SHFLs per acc entry at the end.
// ============================================================================
__global__ __launch_bounds__(256, 2) void k1_stats(const float4* __restrict__ in4) {
    __shared__ __align__(16) unsigned char smem_raw[32768];
    float* red = (float*)smem_raw;

    const int t   = threadIdx.x;
    const int bid = blockIdx.x;
    const int w   = t >> 5;
    const int l   = t & 31;
    const int h   = l >> 4;         // half: even/odd samples
    const int ti  = (l >> 2) & 3;   // i channels 8ti..8ti+7
    const int tj  = l & 3;          // j channels 8tj..8tj+7
    const int sl  = l & 7;          // staging slot (channels 4sl..4sl+3)

    float* wstf = (float*)(smem_raw + w * (WBUF_F * 4));

    u64 acc[8][4];
#pragma unroll
    for (int i = 0; i < 8; i++)
#pragma unroll
        for (int j = 0; j < 4; j++) acc[i][j] = 0ull;

    float msum[4] = {0.f, 0.f, 0.f, 0.f};   // channels 4sl + c

    const long wbase4 = (long)bid * (P1_ROWS * 8) + (long)w * (P1_WROWS * 8);

    // prefetch chunk 0: 16 samples = 128 float4; lane loads f = l + 32*kk
    float4 v[4];
#pragma unroll
    for (int kk = 0; kk < 4; kk++) v[kk] = in4[wbase4 + l + 32 * kk];

    for (int c = 0; c < P1_CHUNKS; c++) {
        __syncwarp();   // prior chunk's reads done before overwrite
        // ---- stage raw row-major + channel sums ----
#pragma unroll
        for (int kk = 0; kk < 4; kk++) {
            int f = l + 32 * kk;
            int s = f >> 3;
            msum[0] += v[kk].x; msum[1] += v[kk].y;
            msum[2] += v[kk].z; msum[3] += v[kk].w;
            *(float4*)(wstf + s * ZR + 4 * sl) = v[kk];
        }
        // ---- prefetch next chunk ----
        if (c + 1 < P1_CHUNKS) {
            long nb = wbase4 + (long)(c + 1) * (P1_CHUNK * 8);
#pragma unroll
            for (int kk = 0; kk < 4; kk++) v[kk] = in4[nb + l + 32 * kk];
        }
        __syncwarp();   // stores visible
        // ---- compute: half h processes samples 2ss+h ----
#pragma unroll
        for (int ss = 0; ss < 8; ss++) {
            const float* row = wstf + (2 * ss + h) * ZR;
            float4 zia = *(const float4*)(row + 8 * ti);
            float4 zib = *(const float4*)(row + 8 * ti + 4);
            ulonglong2 zj0 = *(const ulonglong2*)(row + 8 * tj);
            ulonglong2 zj1 = *(const ulonglong2*)(row + 8 * tj + 4);
            u64 zj[4];
            zj[0] = zj0.x; zj[1] = zj0.y; zj[2] = zj1.x; zj[3] = zj1.y;
            u64 zi[8];
            zi[0] = pack2(zia.x, zia.x); zi[1] = pack2(zia.y, zia.y);
            zi[2] = pack2(zia.z, zia.z); zi[3] = pack2(zia.w, zia.w);
            zi[4] = pack2(zib.x, zib.x); zi[5] = pack2(zib.y, zib.y);
            zi[6] = pack2(zib.z, zib.z); zi[7] = pack2(zib.w, zib.w);
#pragma unroll
            for (int i = 0; i < 8; i++)
#pragma unroll
                for (int j = 0; j < 4; j++)
                    acc[i][j] = ffma2(zi[i], zj[j], acc[i][j]);
        }
    }
    __syncthreads();
    // ---- merge halves (l <-> l^16), write per-warp partials ----
#pragma unroll
    for (int i = 0; i < 8; i++)
#pragma unroll
        for (int j = 0; j < 4; j++) {
            float2 x = unpack2(acc[i][j]);
            float s0 = x.x + __shfl_xor_sync(0xffffffffu, x.x, 16);
            float s1 = x.y + __shfl_xor_sync(0xffffffffu, x.y, 16);
            if (h == 0) {
                red[w * 1024 + (8 * ti + i) * 32 + 8 * tj + 2 * j]     = s0;
                red[w * 1024 + (8 * ti + i) * 32 + 8 * tj + 2 * j + 1] = s1;
            }
        }
    __syncthreads();
    // ---- block reduce C (deterministic order) ----
#pragma unroll
    for (int r = 0; r < 4; r++) {
        int e = t + 256 * r;
        float s = 0.f;
#pragma unroll
        for (int ww = 0; ww < 8; ww++) s += red[ww * 1024 + e];
        gCovPart[(long)bid * 1024 + e] = s;
    }
    __syncthreads();
    // ---- block reduce channel sums ----
    red[t * 4 + 0] = msum[0]; red[t * 4 + 1] = msum[1];
    red[t * 4 + 2] = msum[2]; red[t * 4 + 3] = msum[3];
    __syncthreads();
    if (t < 32) {
        int kk = t >> 2, i = t & 3;
        float s = 0.f;
#pragma unroll 8
        for (int q = 0; q < 32; q++) s += red[(q * 8 + kk) * 4 + i];
        gSumPart[bid * 32 + t] = s;
    }
}

// ============================================================================
// Kernel 1b: fold 2048 partials -> 256
// ============================================================================
__global__ __launch_bounds__(256) void k_red() {
    const int t = threadIdx.x;
    const int bid = blockIdx.x;
    const long base = (long)bid * RED_FOLD;

#pragma unroll
    for (int r = 0; r < 4; r++) {
        int e = t + 256 * r;
        float s = 0.f;
#pragma unroll
        for (int f = 0; f < RED_FOLD; f++) s += gCovPart[(base + f) * 1024 + e];
        gCov2[(long)bid * 1024 + e] = s;
    }
    if (t < 32) {
        float s = 0.f;
#pragma unroll
        for (int f = 0; f < RED_FOLD; f++) s += gSumPart[(base + f) * 32 + t];
        gSum2[bid * 32 + t] = s;
    }
}

// ============================================================================
// Kernel 2: final reduce, build S, normalize, Newton-Schulz, emit Mt+bias.
// ============================================================================
__global__ __launch_bounds__(1024) void k_solve() {
    __shared__ float S[1024], B[1024], T1[1024], T2[1024];
    __shared__ float mu[32];
    __shared__ float redw[32];
    __shared__ float normsh;

    const int t = threadIdx.x;
    const int g = blockIdx.x;
    const int i = t >> 5, j = t & 31;

    float cv = 0.f;
    const float* cp = gCov2 + (long)g * RED_SLICES * 1024;
#pragma unroll 8
    for (int bb = 0; bb < RED_SLICES; bb++) cv += cp[bb * 1024 + t];
    if (t < 32) {
        float s = 0.f;
        const float* sp = gSum2 + g * RED_SLICES * 32;
#pragma unroll 8
        for (int bb = 0; bb < RED_SLICES; bb++) s += sp[bb * 32 + t];
        mu[t] = s * (1.0f / (float)ROWS_PER_GROUP);
    }
    __syncthreads();

    float sij = cv - (float)ROWS_PER_GROUP * mu[i] * mu[j] + ((i == j) ? EPSV : 0.f);

    float v = sij * sij;
#pragma unroll
    for (int o = 16; o; o >>= 1) v += __shfl_xor_sync(0xffffffffu, v, o);
    if (j == 0) redw[i] = v;
    __syncthreads();
    if (t < 32) {
        float x = redw[t];
#pragma unroll
        for (int o = 16; o; o >>= 1) x += __shfl_xor_sync(0xffffffffu, x, o);
        if (t == 0) normsh = sqrtf(x);
    }
    __syncthreads();
    const float nrm = normsh;

    S[t] = sij / nrm;
    B[t] = (i == j) ? 1.f : 0.f;
    __syncthreads();

    for (int it = 0; it < TITER; it++) {
        float s1 = 0.f;
#pragma unroll
        for (int kk = 0; kk < 32; kk++) s1 += B[i * 32 + kk] * B[kk * 32 + j];
        T1[t] = s1; __syncthreads();
        float s2 = 0.f;
#pragma unroll
        for (int kk = 0; kk < 32; kk++) s2 += T1[i * 32 + kk] * B[kk * 32 + j];
        T2[t] = s2; __syncthreads();
        float s3 = 0.f;
#pragma unroll
        for (int kk = 0; kk < 32; kk++) s3 += T2[i * 32 + kk] * S[kk * 32 + j];
        float nb = 1.5f * B[t] - 0.5f * s3;
        __syncthreads();
        B[t] = nb;
        __syncthreads();
    }

    const float inv = rsqrtf(nrm);
    float mt = B[j * 32 + i] * inv;
    gMt[g * 1024 + t] = mt;
    T1[t] = mt;
    __syncthreads();
    if (t < 32) {
        float bsum = 0.f;
#pragma unroll
        for (int d = 0; d < 32; d++) bsum += mu[d] * T1[d * 32 + t];
        gBias[g * 32 + t] = -bsum;
    }
}

// ============================================================================
// Kernel 3: out[n] = z[n] @ Mt + bias. Exact revert to measured-103.5 variant.
// 128 threads: m = t&3 (channels 8m..8m+7), q = t>>2 (0..31),
// rows q + 32*rr, rr<8. Per dp: 4 LDS.128 Mt (quad-broadcast) serve 8 rows;
// z via 8 lane-distinct LDS.64.
// ============================================================================
__global__ __launch_bounds__(P2_TPB, 3) void k2_apply(const float4* __restrict__ in4,
                                                      float4* __restrict__ out4) {
    __shared__ __align__(16) float zbuf[P2_ROWS * ZST];  // 34816 B
    __shared__ __align__(16) u64 mt2[512];
    __shared__ u64 bias2[16];

    const int t = threadIdx.x;
    const int g = blockIdx.x >> 10;          // 1024 blocks per group

    const u64* mtg = (const u64*)gMt + g * 512;
#pragma unroll
    for (int i = 0; i < 4; i++) mt2[t + 128 * i] = mtg[t + 128 * i];
    if (t < 16) bias2[t] = ((const u64*)gBias)[g * 16 + t];

    const int m = t & 3;
    const int q = t >> 2;                    // 0..31
    const long R0 = (long)blockIdx.x * P2_ROWS;

    // ---- stage 256 rows: coalesced LDG.128, float2 smem stores ----
#pragma unroll
    for (int i = 0; i < 16; i++) {
        int f = t + 128 * i;                 // float4 id in tile
        int row = f >> 3, sl = f & 7;
        float4 v = in4[R0 * 8 + f];
        float2* d = (float2*)(zbuf + row * ZST + 4 * sl);
        d[0] = make_float2(v.x, v.y);
        d[1] = make_float2(v.z, v.w);
    }
    __syncthreads();

    u64 acc[8][4];
#pragma unroll
    for (int rr = 0; rr < 8; rr++)
#pragma unroll
        for (int jj = 0; jj < 4; jj++) acc[rr][jj] = bias2[m * 4 + jj];

    const ulonglong2* mtv = (const ulonglong2*)mt2;
#pragma unroll 4
    for (int dp = 0; dp < 16; dp++) {
        const int d0 = 2 * dp;
        ulonglong2 ma0 = mtv[d0 * 8 + m * 2 + 0];
        ulonglong2 mb0 = mtv[d0 * 8 + m * 2 + 1];
        ulonglong2 ma1 = mtv[d0 * 8 + m * 2 + 8];   // (d0+1)
        ulonglong2 mb1 = mtv[d0 * 8 + m * 2 + 9];
#pragma unroll
        for (int rr = 0; rr < 8; rr++) {
            float2 z2 = *(const float2*)(zbuf + (q + 32 * rr) * ZST + d0);
            u64 zz0 = pack2(z2.x, z2.x);
            u64 zz1 = pack2(z2.y, z2.y);
            acc[rr][0] = ffma2(zz0, ma0.x, acc[rr][0]);
            acc[rr][1] = ffma2(zz0, ma0.y, acc[rr][1]);
            acc[rr][2] = ffma2(zz0, mb0.x, acc[rr][2]);
            acc[rr][3] = ffma2(zz0, mb0.y, acc[rr][3]);
            acc[rr][0] = ffma2(zz1, ma1.x, acc[rr][0]);
            acc[rr][1] = ffma2(zz1, ma1.y, acc[rr][1]);
            acc[rr][2] = ffma2(zz1, mb1.x, acc[rr][2]);
            acc[rr][3] = ffma2(zz1, mb1.y, acc[rr][3]);
        }
    }

#pragma unroll
    for (int rr = 0; rr < 8; rr++) {
        float2 p0 = unpack2(acc[rr][0]), p1 = unpack2(acc[rr][1]);
        float2 p2 = unpack2(acc[rr][2]), p3 = unpack2(acc[rr][3]);
        long rowb = (R0 + q + 32 * rr) * 8;
        out4[rowb + m * 2 + 0] = make_float4(p0.x, p0.y, p1.x, p1.y);
        out4[rowb + m * 2 + 1] = make_float4(p2.x, p2.y, p3.x, p3.y);
    }
}

// ============================================================================
extern "C" void kernel_launch(void* const* d_in, const int* in_sizes, int n_in,
                              void* d_out, int out_size) {
    const float4* in4 = (const float4*)d_in[0];
    float4* out4 = (float4*)d_out;

    k1_stats<<<P1_GRID, 256>>>(in4);
    k_red<<<GROUPS * RED_SLICES, 256>>>();
    k_solve<<<GROUPS, 1024>>>();
    k2_apply<<<P2_GRID, P2_TPB>>>(in4, out4);
}